// round 12
// baseline (speedup 1.0000x reference)
#include <cuda_runtime.h>
#include <cuda_bf16.h>
#include <cstdint>

#define BB 32
#define TT 64
#define NNODE 207
#define FF 64
#define HH 128
#define MM (BB * NNODE)      // 6624
#define MTILE 96
#define GRIDM 69             // 6624 / 96
#define NTH 384

// packed bf16 hi/lo weights, fragment-native (m16n8k16) layout.
// u32 index: (((k16*48 + ntile)*2 + hilo)*32 + lane)*2 + {0,1}
// u32 region bases: L0IH 0 | L0HH 24576 | L1IH 73728 | L1HH 122880
#define WPU_TOTAL (86016 * 2)
__device__ unsigned g_wp[WPU_TOTAL];

// smem layout (u32 units):
// XF[6144] | H0F[12288] | H1F[12288] | BIAS[1536] | BBUF[3 x 6144]
#define XF_OFF 0
#define H0F_OFF 6144
#define H1F_OFF 18432
#define BIAS_OFF 30720
#define BB_OFF 32256
#define BCH_U32 6144          // one 2-kstep HALF-width B chunk = 24.6KB
#define SM_U32 (32256 + 3 * 6144)   // 50688 u32 = 202,752 B

// ---------------- weight prepack (layout validated R6/R8/R10) ----------------
__global__ void prep_kernel(const float* __restrict__ Wih0, const float* __restrict__ Whh0,
                            const float* __restrict__ Wih1, const float* __restrict__ Whh1)
{
    __nv_bfloat16* wp = reinterpret_cast<__nv_bfloat16*>(g_wp);
    const float* srcs[4] = {Wih0, Whh0, Wih1, Whh1};
    const int Ks[4]   = {64, 128, 128, 128};
    const int offs[4] = {0, 24576 * 2, 73728 * 2, 122880 * 2};   // bf16 offsets
    const int total = (64 + 128 + 128 + 128) * 384;
    for (int idx = blockIdx.x * blockDim.x + threadIdx.x; idx < total;
         idx += gridDim.x * blockDim.x) {
        int m, rem = idx;
        for (m = 0; m < 4; m++) {
            int sz = Ks[m] * 384;
            if (rem < sz) break;
            rem -= sz;
        }
        int k = rem / 384;
        int p = rem % 384;
        int w16 = p / 48, g = (p % 48) / 16, jj = p % 16;
        float v = srcs[m][(size_t)k * 384 + g * 128 + w16 * 16 + jj];
        __nv_bfloat16 hb = __float2bfloat16_rn(v);
        __nv_bfloat16 lb = __float2bfloat16_rn(v - __bfloat162float(hb));
        int k16 = k >> 4, kk = k & 15;
        int nt = p >> 3;
        int lane = (p & 7) * 4 + ((kk & 7) >> 1);
        int slot = kk >> 3;
        int hw = kk & 1;
        int ib = (((k16 * 48 + nt) * 2) * 32 + lane) * 4 + slot * 2 + hw;
        wp[offs[m] + ib] = hb;
        wp[offs[m] + ib + 128] = lb;
    }
}

#define MMA_B(D, A, B)                                                            \
    asm volatile(                                                                 \
        "mma.sync.aligned.m16n8k16.row.col.f32.bf16.bf16.f32 "                    \
        "{%0,%1,%2,%3},{%4,%5,%6,%7},{%8,%9},{%0,%1,%2,%3};\n"                    \
        : "+f"(D[0]), "+f"(D[1]), "+f"(D[2]), "+f"(D[3])                          \
        : "r"(A.x), "r"(A.y), "r"(A.z), "r"(A.w), "r"(B.x), "r"(B.y))

__device__ __forceinline__ void split_pack(float vx, float vy, unsigned& hi, unsigned& lo) {
    __nv_bfloat16 hx = __float2bfloat16_rn(vx);
    __nv_bfloat16 hy = __float2bfloat16_rn(vy);
    __nv_bfloat16 lx = __float2bfloat16_rn(vx - __bfloat162float(hx));
    __nv_bfloat16 ly = __float2bfloat16_rn(vy - __bfloat162float(hy));
    hi = (unsigned)__bfloat16_as_ushort(hx) | ((unsigned)__bfloat16_as_ushort(hy) << 16);
    lo = (unsigned)__bfloat16_as_ushort(lx) | ((unsigned)__bfloat16_as_ushort(ly) << 16);
}

__device__ __forceinline__ float2 unsplit(unsigned hi, unsigned lo) {
    float hx = __bfloat162float(__ushort_as_bfloat16((unsigned short)(hi & 0xffff)));
    float hy = __bfloat162float(__ushort_as_bfloat16((unsigned short)(hi >> 16)));
    float lx = __bfloat162float(__ushort_as_bfloat16((unsigned short)(lo & 0xffff)));
    float ly = __bfloat162float(__ushort_as_bfloat16((unsigned short)(lo >> 16)));
    return make_float2(hx + lx, hy + ly);
}

__device__ __forceinline__ float fsigmoid(float x) {
    return __fdividef(1.f, 1.f + __expf(-x));
}
__device__ __forceinline__ float ftanh(float x) {
    return __fdividef(2.f, 1.f + __expf(-2.f * x)) - 1.f;
}

// load x[t] (K=64 -> ksteps 0..3) into XF in fragment-native form
__device__ __forceinline__ void load_x(unsigned* XF, const float* __restrict__ x,
                                       int mb, int t, int tid)
{
#pragma unroll
    for (int it = 0; it < 2; it++) {
        int s = tid + it * NTH;
        int ln = s & 31;
        int t2 = s >> 5;
        int mt = t2 % 6, ksl = t2 / 6;
        int r0 = mb + mt * 16 + (ln >> 2);
        int c0 = ksl * 16 + (ln & 3) * 2;
        int b0 = r0 / NNODE, n0 = r0 - b0 * NNODE;
        int r1 = r0 + 8;
        int b1 = r1 / NNODE, n1 = r1 - b1 * NNODE;
        const float* p0 = x + (size_t)((b0 * TT + t) * NNODE + n0) * FF;
        const float* p1 = x + (size_t)((b1 * TT + t) * NNODE + n1) * FF;
        float2 v00 = *(const float2*)(p0 + c0);
        float2 v01 = *(const float2*)(p0 + c0 + 8);
        float2 v10 = *(const float2*)(p1 + c0);
        float2 v11 = *(const float2*)(p1 + c0 + 8);
        unsigned h0, l0, h1, l1, h2, l2, h3, l3;
        split_pack(v00.x, v00.y, h0, l0);
        split_pack(v10.x, v10.y, h1, l1);
        split_pack(v01.x, v01.y, h2, l2);
        split_pack(v11.x, v11.y, h3, l3);
        *(uint4*)(XF + (t2 * 2 + 0) * 128 + ln * 4) = make_uint4(h0, h1, h2, h3);
        *(uint4*)(XF + (t2 * 2 + 1) * 128 + ln * 4) = make_uint4(l0, l1, l2, l3);
    }
}

// u32 offset of chunk c (0..13) within g_wp.
// FULL-width (48-ntile) stride per 2-kstep chunk = 2*48*2*32*2 = 12288 u32.
__device__ __forceinline__ int chunk_woff(int c) {
    if (c < 2)  return c * 12288;                    // L0 Wih ks 0-3
    if (c < 6)  return 24576 + (c - 2) * 12288;      // L0 Whh ks 0-7
    if (c < 10) return 73728 + (c - 6) * 12288;      // L1 Wih ks 0-7
    return 122880 + (c - 10) * 12288;                // L1 Whh ks 0-7
}

// async-copy one 2-kstep B chunk (our half's 24 ntiles) into a smem ring buffer
__device__ __forceinline__ void prefetch_chunk(const unsigned* __restrict__ wsrc,
                                               unsigned* bbuf, int half, int tid)
{
    unsigned dst_base = (unsigned)__cvta_generic_to_shared(bbuf);
#pragma unroll
    for (int j = 0; j < 4; j++) {
        int i = tid + j * NTH;           // 0..1535
        int c16 = i & 15;
        int hilo = (i >> 4) & 1;
        int r = i >> 5;                  // 0..47
        int ksl = (r >= 24) ? 1 : 0;
        int ntl = r - ksl * 24;
        int so = ((ksl * 48 + half * 24 + ntl) * 2 + hilo) * 64 + c16 * 4;
        int dofs = ((ksl * 24 + ntl) * 2 + hilo) * 64 + c16 * 4;
        asm volatile("cp.async.ca.shared.global [%0], [%1], 16;\n"
                     :: "r"(dst_base + dofs * 4), "l"(wsrc + so) : "memory");
    }
    asm volatile("cp.async.commit_group;\n" ::: "memory");
}

// 2-kstep MMA: A from smem frag region (aks0 base), B from smem chunk buffer
__device__ __forceinline__ void mma_chunk2(const unsigned* af, int aks0,
                                           const unsigned* bb,
                                           int wn, int wm, int lane, float (*acc)[6][4])
{
#pragma unroll
    for (int ksl = 0; ksl < 2; ksl++) {
        uint4 ah[2], al[2];
#pragma unroll
        for (int m = 0; m < 2; m++) {
            int t2 = (aks0 + ksl) * 6 + wm * 2 + m;
            ah[m] = *(const uint4*)(af + (t2 * 2 + 0) * 128 + lane * 4);
            al[m] = *(const uint4*)(af + (t2 * 2 + 1) * 128 + lane * 4);
        }
        uint2 bh[6], bl[6];
#pragma unroll
        for (int n = 0; n < 6; n++) {
            int off = ((ksl * 24 + wn * 6 + n) * 2) * 64 + lane * 2;
            bh[n] = *(const uint2*)(bb + off);
            bl[n] = *(const uint2*)(bb + off + 64);
        }
#pragma unroll
        for (int m = 0; m < 2; m++)
#pragma unroll
            for (int n = 0; n < 6; n++) {
                MMA_B(acc[m][n], ah[m], bh[n]);
                MMA_B(acc[m][n], ah[m], bl[n]);
                MMA_B(acc[m][n], al[m], bh[n]);
            }
    }
}

__device__ __forceinline__ void cluster_sync_() {
    __syncthreads();
    asm volatile("barrier.cluster.arrive.aligned;" ::: "memory");
    asm volatile("barrier.cluster.wait.aligned;" ::: "memory");
}

__device__ __forceinline__ void st_peer(unsigned peer_addr, unsigned v) {
    asm volatile("st.shared::cluster.u32 [%0], %1;" :: "r"(peer_addr), "r"(v) : "memory");
}

template <bool WOUT>
__device__ __forceinline__ void gru_epilogue(
    unsigned* HF, unsigned peerHF,
    const float (*acc0)[6][4], const float (*acc1)[6][4],
    const float* __restrict__ bi, const float* __restrict__ bh,
    float* __restrict__ Oout, float* __restrict__ Hfin,
    int t, int mb, int half, int wm, int wn, int lane, bool write_fin)
{
    const int w16 = half * 4 + wn;
    const int jq = (lane & 3) * 2;
    const int lane4 = lane >> 2;

    float BI[3][2][2], BHh[3][2][2];
#pragma unroll
    for (int nb = 0; nb < 2; nb++)
#pragma unroll
        for (int ci = 0; ci < 2; ci++) {
            int j = w16 * 16 + nb * 8 + jq + ci;
            BI[0][nb][ci] = bi[j];       BI[1][nb][ci] = bi[128 + j];
            BI[2][nb][ci] = bi[256 + j];
            BHh[0][nb][ci] = bh[j];      BHh[1][nb][ci] = bh[128 + j];
            BHh[2][nb][ci] = bh[256 + j];
        }

#pragma unroll
    for (int m = 0; m < 2; m++) {
#pragma unroll
        for (int h8 = 0; h8 < 2; h8++) {
            int gm = mb + wm * 32 + m * 16 + lane4 + h8 * 8;
            int ob = gm / NNODE;
            int on = gm - ob * NNODE;
            size_t obase = WOUT ? ((size_t)((ob * TT + t) * NNODE + on) * HH) : 0;
#pragma unroll
            for (int nb = 0; nb < 2; nb++) {
                int j0 = w16 * 16 + nb * 8 + jq;
                int base = ((w16 * 6 + wm * 2 + m) * 2) * 128 + lane * 4 + (nb * 2 + h8);
                float2 hp = unsplit(HF[base], HF[base + 128]);
                int c = h8 * 2;
                float hv[2];
#pragma unroll
                for (int ci = 0; ci < 2; ci++) {
                    float ir = acc0[m][nb][c + ci]     + BI[0][nb][ci];
                    float iz = acc0[m][nb + 2][c + ci] + BI[1][nb][ci];
                    float in_ = acc0[m][nb + 4][c + ci] + BI[2][nb][ci];
                    float hr = acc1[m][nb][c + ci]     + BHh[0][nb][ci];
                    float hz = acc1[m][nb + 2][c + ci] + BHh[1][nb][ci];
                    float hn = acc1[m][nb + 4][c + ci] + BHh[2][nb][ci];
                    float r = fsigmoid(ir + hr);
                    float z = fsigmoid(iz + hz);
                    float nn = ftanh(in_ + r * hn);
                    float hpv = ci ? hp.y : hp.x;
                    hv[ci] = (1.f - z) * nn + z * hpv;
                }
                unsigned hi, lo;
                split_pack(hv[0], hv[1], hi, lo);
                HF[base] = hi;
                HF[base + 128] = lo;
                st_peer(peerHF + base * 4, hi);
                st_peer(peerHF + (base + 128) * 4, lo);
                if (WOUT)
                    *(float2*)&Oout[obase + j0] = make_float2(hv[0], hv[1]);
                if (write_fin)
                    *(float2*)&Hfin[(size_t)gm * HH + j0] = make_float2(hv[0], hv[1]);
            }
        }
    }
}

// persistent kernel: all 64 timesteps, both layers; H state in smem frags;
// weights streamed via cp.async 3-buffer ring (2-kstep chunks, depth 2).
__global__ void __launch_bounds__(NTH, 1) __cluster_dims__(1, 2, 1)
gru_persist(const float* __restrict__ x,
            const float* __restrict__ bih0, const float* __restrict__ bhh0,
            const float* __restrict__ bih1, const float* __restrict__ bhh1,
            float* __restrict__ out, float* __restrict__ h0f, float* __restrict__ h1f)
{
    extern __shared__ unsigned sm[];
    unsigned* XF = sm + XF_OFF;
    unsigned* H0F = sm + H0F_OFF;
    unsigned* H1F = sm + H1F_OFF;
    float* BS = (float*)(sm + BIAS_OFF);
    unsigned* BBuf = sm + BB_OFF;

    const int tid = threadIdx.x;
    const int mb = blockIdx.x * MTILE;
    const int half = blockIdx.y;
    const int wid = tid >> 5, lane = tid & 31;
    const int wm = wid >> 2, wn = wid & 3;

    unsigned peer_h0, peer_h1, rank;
    asm("mov.u32 %0, %%cluster_ctarank;" : "=r"(rank));
    {
        unsigned a0, a1;
        asm("{ .reg .u64 t; cvta.to.shared.u64 t, %1; cvt.u32.u64 %0, t; }"
            : "=r"(a0) : "l"(H0F));
        asm("{ .reg .u64 t; cvta.to.shared.u64 t, %1; cvt.u32.u64 %0, t; }"
            : "=r"(a1) : "l"(H1F));
        unsigned pr = rank ^ 1;
        asm("mapa.shared::cluster.u32 %0, %1, %2;" : "=r"(peer_h0) : "r"(a0), "r"(pr));
        asm("mapa.shared::cluster.u32 %0, %1, %2;" : "=r"(peer_h1) : "r"(a1), "r"(pr));
    }

    // init: h0 = h1 = 0 ; stage biases
    for (int i = tid; i < 24576; i += NTH) H0F[i] = 0u;
    for (int i = tid; i < 384; i += NTH) {
        BS[i]        = bih0[i];
        BS[384 + i]  = bhh0[i];
        BS[768 + i]  = bih1[i];
        BS[1152 + i] = bhh1[i];
    }
    __syncthreads();

    // prime the cp.async pipeline: chunks 0, 1
    prefetch_chunk(g_wp + chunk_woff(0), BBuf + 0 * BCH_U32, half, tid);
    prefetch_chunk(g_wp + chunk_woff(1), BBuf + 1 * BCH_U32, half, tid);
    int q = 0;   // global chunk counter

    float acc0[2][6][4], acc1[2][6][4];

#pragma unroll 1
    for (int t = 0; t < TT; t++) {
        load_x(XF, x, mb, t, tid);

#pragma unroll
        for (int m = 0; m < 2; m++)
#pragma unroll
            for (int n = 0; n < 6; n++)
#pragma unroll
                for (int c = 0; c < 4; c++) { acc0[m][n][c] = 0.f; acc1[m][n][c] = 0.f; }

#pragma unroll 1
        for (int c = 0; c < 14; c++) {
            // wait for chunk q (allow chunk q+1 outstanding), make copies visible
            asm volatile("cp.async.wait_group 1;\n" ::: "memory");
            __syncthreads();

            const unsigned* bb = BBuf + (q % 3) * BCH_U32;
            if (c < 2)        mma_chunk2(XF,  c * 2,        bb, wn, wm, lane, acc0);
            else if (c < 6)   mma_chunk2(H0F, (c - 2) * 2,  bb, wn, wm, lane, acc1);
            else if (c < 10)  mma_chunk2(H0F, (c - 6) * 2,  bb, wn, wm, lane, acc0);
            else              mma_chunk2(H1F, (c - 10) * 2, bb, wn, wm, lane, acc1);

            // prefetch chunk q+2 (buffer consumed at chunk q-1; ordered by the
            // sync above). Issued BEFORE any barriers/epilogue so the copy
            // engine covers those serial phases. Wraps harmlessly at the end.
            int qn = q + 2;
            prefetch_chunk(g_wp + chunk_woff(qn % 14),
                           BBuf + (qn % 3) * BCH_U32, half, tid);
            q++;

            if (c == 5) {
                cluster_sync_();                 // B1: peers done reading old H0F
                gru_epilogue<false>(H0F, peer_h0, acc0, acc1, BS, BS + 384,
                                    (float*)nullptr, h0f, t, mb, half, wm, wn, lane,
                                    t == TT - 1);
                cluster_sync_();                 // B2: new H0F visible
#pragma unroll
                for (int m = 0; m < 2; m++)
#pragma unroll
                    for (int n = 0; n < 6; n++)
#pragma unroll
                        for (int cc = 0; cc < 4; cc++) { acc0[m][n][cc] = 0.f; acc1[m][n][cc] = 0.f; }
            }
        }

        cluster_sync_();                         // B3: peers done reading old H1F
        gru_epilogue<true>(H1F, peer_h1, acc0, acc1, BS + 768, BS + 1152,
                           out, h1f, t, mb, half, wm, wn, lane, t == TT - 1);
        // epi1 H1F writes ordered for peer by next step's B1+B2
    }

    // drain async copies, then final cluster barrier (peer DSMEM stores)
    asm volatile("cp.async.wait_group 0;\n" ::: "memory");
    cluster_sync_();
}

extern "C" void kernel_launch(void* const* d_in, const int* in_sizes, int n_in,
                              void* d_out, int out_size)
{
    const float* x    = (const float*)d_in[0];
    const float* Wih0 = (const float*)d_in[1];
    const float* Whh0 = (const float*)d_in[2];
    const float* bih0 = (const float*)d_in[3];
    const float* bhh0 = (const float*)d_in[4];
    const float* Wih1 = (const float*)d_in[5];
    const float* Whh1 = (const float*)d_in[6];
    const float* bih1 = (const float*)d_in[7];
    const float* bhh1 = (const float*)d_in[8];

    float* out = (float*)d_out;
    float* h0f = out + (size_t)BB * TT * NNODE * HH;
    float* h1f = h0f + (size_t)MM * HH;

    cudaFuncSetAttribute((const void*)gru_persist,
                         cudaFuncAttributeMaxDynamicSharedMemorySize, SM_U32 * 4);

    prep_kernel<<<168, 256>>>(Wih0, Whh0, Wih1, Whh1);
    gru_persist<<<dim3(GRIDM, 2), NTH, SM_U32 * 4>>>(
        x, bih0, bhh0, bih1, bhh1, out, h0f, h1f);
}

// round 13
// speedup vs baseline: 1.1489x; 1.1489x over previous
#include <cuda_runtime.h>
#include <cuda_bf16.h>
#include <cstdint>

#define BB 32
#define TT 64
#define NNODE 207
#define FF 64
#define HH 128
#define MM (BB * NNODE)      // 6624
#define MTILE 96
#define GRIDM 69             // 6624 / 96
#define NTH 384

// packed bf16 hi/lo weights, fragment-native (m16n8k16) layout.
// uint2 unit index: ((k16*48 + ntile)*2 + hilo)*32 + lane ; uint2 = {b0,b1}
#define WPU2_L0IH 0
#define WPU2_L0HH 12288      // 4*48*2*32
#define WPU2_L1IH 36864
#define WPU2_L1HH 61440
#define WPU2_TOTAL 86016
__device__ unsigned g_wp[WPU2_TOTAL * 2];

// smem layout (u32 units):
// XF[6144] | H0F[12288] | H1F[12288] | BIAS[1536] | GIS[18432]
#define XF_OFF 0
#define H0F_OFF 6144
#define H1F_OFF 18432
#define BIAS_OFF 30720
#define GIS_OFF 32256
#define SM_U32 (32256 + 18432)    // 50688 u32 = 202,752 B

// ---------------- weight prepack (layout validated R6/R8/R10) ----------------
__global__ void prep_kernel(const float* __restrict__ Wih0, const float* __restrict__ Whh0,
                            const float* __restrict__ Wih1, const float* __restrict__ Whh1)
{
    __nv_bfloat16* wp = reinterpret_cast<__nv_bfloat16*>(g_wp);
    const float* srcs[4] = {Wih0, Whh0, Wih1, Whh1};
    const int Ks[4]   = {64, 128, 128, 128};
    const int offs[4] = {WPU2_L0IH * 4, WPU2_L0HH * 4, WPU2_L1IH * 4, WPU2_L1HH * 4};
    const int total = (64 + 128 + 128 + 128) * 384;
    for (int idx = blockIdx.x * blockDim.x + threadIdx.x; idx < total;
         idx += gridDim.x * blockDim.x) {
        int m, rem = idx;
        for (m = 0; m < 4; m++) {
            int sz = Ks[m] * 384;
            if (rem < sz) break;
            rem -= sz;
        }
        int k = rem / 384;
        int p = rem % 384;
        int w16 = p / 48, g = (p % 48) / 16, jj = p % 16;
        float v = srcs[m][(size_t)k * 384 + g * 128 + w16 * 16 + jj];
        __nv_bfloat16 hb = __float2bfloat16_rn(v);
        __nv_bfloat16 lb = __float2bfloat16_rn(v - __bfloat162float(hb));
        int k16 = k >> 4, kk = k & 15;
        int nt = p >> 3;
        int lane = (p & 7) * 4 + ((kk & 7) >> 1);
        int slot = kk >> 3;
        int hw = kk & 1;
        int ib = (((k16 * 48 + nt) * 2) * 32 + lane) * 4 + slot * 2 + hw;
        wp[offs[m] + ib] = hb;
        wp[offs[m] + ib + 128] = lb;
    }
}

#define MMA_B(D, A, B)                                                            \
    asm volatile(                                                                 \
        "mma.sync.aligned.m16n8k16.row.col.f32.bf16.bf16.f32 "                    \
        "{%0,%1,%2,%3},{%4,%5,%6,%7},{%8,%9},{%0,%1,%2,%3};\n"                    \
        : "+f"(D[0]), "+f"(D[1]), "+f"(D[2]), "+f"(D[3])                          \
        : "r"(A.x), "r"(A.y), "r"(A.z), "r"(A.w), "r"(B.x), "r"(B.y))

__device__ __forceinline__ void split_pack(float vx, float vy, unsigned& hi, unsigned& lo) {
    __nv_bfloat16 hx = __float2bfloat16_rn(vx);
    __nv_bfloat16 hy = __float2bfloat16_rn(vy);
    __nv_bfloat16 lx = __float2bfloat16_rn(vx - __bfloat162float(hx));
    __nv_bfloat16 ly = __float2bfloat16_rn(vy - __bfloat162float(hy));
    hi = (unsigned)__bfloat16_as_ushort(hx) | ((unsigned)__bfloat16_as_ushort(hy) << 16);
    lo = (unsigned)__bfloat16_as_ushort(lx) | ((unsigned)__bfloat16_as_ushort(ly) << 16);
}

__device__ __forceinline__ float2 unsplit(unsigned hi, unsigned lo) {
    float hx = __bfloat162float(__ushort_as_bfloat16((unsigned short)(hi & 0xffff)));
    float hy = __bfloat162float(__ushort_as_bfloat16((unsigned short)(hi >> 16)));
    float lx = __bfloat162float(__ushort_as_bfloat16((unsigned short)(lo & 0xffff)));
    float ly = __bfloat162float(__ushort_as_bfloat16((unsigned short)(lo >> 16)));
    return make_float2(hx + lx, hy + ly);
}

__device__ __forceinline__ float fsigmoid(float x) {
    return __fdividef(1.f, 1.f + __expf(-x));
}
__device__ __forceinline__ float ftanh(float x) {
    return __fdividef(2.f, 1.f + __expf(-2.f * x)) - 1.f;
}

// load x[t] (K=64 -> ksteps 0..3) into XF in fragment-native form
__device__ __forceinline__ void load_x(unsigned* XF, const float* __restrict__ x,
                                       int mb, int t, int tid)
{
#pragma unroll
    for (int it = 0; it < 2; it++) {
        int s = tid + it * NTH;
        int ln = s & 31;
        int t2 = s >> 5;
        int mt = t2 % 6, ksl = t2 / 6;
        int r0 = mb + mt * 16 + (ln >> 2);
        int c0 = ksl * 16 + (ln & 3) * 2;
        int b0 = r0 / NNODE, n0 = r0 - b0 * NNODE;
        int r1 = r0 + 8;
        int b1 = r1 / NNODE, n1 = r1 - b1 * NNODE;
        const float* p0 = x + (size_t)((b0 * TT + t) * NNODE + n0) * FF;
        const float* p1 = x + (size_t)((b1 * TT + t) * NNODE + n1) * FF;
        float2 v00 = *(const float2*)(p0 + c0);
        float2 v01 = *(const float2*)(p0 + c0 + 8);
        float2 v10 = *(const float2*)(p1 + c0);
        float2 v11 = *(const float2*)(p1 + c0 + 8);
        unsigned h0, l0, h1, l1, h2, l2, h3, l3;
        split_pack(v00.x, v00.y, h0, l0);
        split_pack(v10.x, v10.y, h1, l1);
        split_pack(v01.x, v01.y, h2, l2);
        split_pack(v11.x, v11.y, h3, l3);
        *(uint4*)(XF + (t2 * 2 + 0) * 128 + ln * 4) = make_uint4(h0, h1, h2, h3);
        *(uint4*)(XF + (t2 * 2 + 1) * 128 + ln * 4) = make_uint4(l0, l1, l2, l3);
    }
}

// MMA over NK16 k16-steps: A from smem frag region, B from global weights.
// Only ONE 48-float accumulator set is live here (gi stashed to smem between
// spans) -> ~48 free regs for ptxas to pipeline the B LDGs across ksteps.
template <int NK16>
__device__ __forceinline__ void mma_span(const unsigned* af, const uint2* __restrict__ wb,
                                         int ntb, int wm, int lane, float (*acc)[6][4])
{
#pragma unroll
    for (int ks = 0; ks < NK16; ks++) {
        uint4 ah[2], al[2];
#pragma unroll
        for (int m = 0; m < 2; m++) {
            int t2 = ks * 6 + wm * 2 + m;
            ah[m] = *(const uint4*)(af + (t2 * 2 + 0) * 128 + lane * 4);
            al[m] = *(const uint4*)(af + (t2 * 2 + 1) * 128 + lane * 4);
        }
        uint2 bh[6], bl[6];
#pragma unroll
        for (int n = 0; n < 6; n++) {
            int i2 = ((ks * 48 + ntb + n) * 2) * 32 + lane;
            bh[n] = wb[i2];
            bl[n] = wb[i2 + 32];
        }
#pragma unroll
        for (int m = 0; m < 2; m++)
#pragma unroll
            for (int n = 0; n < 6; n++) {
                MMA_B(acc[m][n], ah[m], bh[n]);
                MMA_B(acc[m][n], ah[m], bl[n]);
                MMA_B(acc[m][n], al[m], bh[n]);
            }
    }
}

__device__ __forceinline__ void cluster_sync_() {
    __syncthreads();
    asm volatile("barrier.cluster.arrive.aligned;" ::: "memory");
    asm volatile("barrier.cluster.wait.aligned;" ::: "memory");
}

__device__ __forceinline__ void st_peer(unsigned peer_addr, unsigned v) {
    asm volatile("st.shared::cluster.u32 [%0], %1;" :: "r"(peer_addr), "r"(v) : "memory");
}

// stash / restore gi accumulators through smem, [slot][tid] layout
// (same-thread only: no syncs needed, stride-384 = conflict-free)
__device__ __forceinline__ void stash_acc(float* GIS, const float (*acc)[6][4], int tid) {
#pragma unroll
    for (int m = 0; m < 2; m++)
#pragma unroll
        for (int n = 0; n < 6; n++)
#pragma unroll
            for (int c = 0; c < 4; c++)
                GIS[(((m * 6 + n) * 4) + c) * NTH + tid] = acc[m][n][c];
}

// GRU epilogue: gi from smem stash, gh in registers.
template <bool WOUT>
__device__ __forceinline__ void gru_epilogue(
    unsigned* HF, unsigned peerHF,
    const float* GIS, const float (*acc1)[6][4],
    const float* __restrict__ bi, const float* __restrict__ bh,
    float* __restrict__ Oout, float* __restrict__ Hfin,
    int t, int mb, int half, int wm, int wn, int lane, int tid, bool write_fin)
{
    const int w16 = half * 4 + wn;
    const int jq = (lane & 3) * 2;
    const int lane4 = lane >> 2;

    float BI[3][2][2], BHh[3][2][2];
#pragma unroll
    for (int nb = 0; nb < 2; nb++)
#pragma unroll
        for (int ci = 0; ci < 2; ci++) {
            int j = w16 * 16 + nb * 8 + jq + ci;
            BI[0][nb][ci] = bi[j];       BI[1][nb][ci] = bi[128 + j];
            BI[2][nb][ci] = bi[256 + j];
            BHh[0][nb][ci] = bh[j];      BHh[1][nb][ci] = bh[128 + j];
            BHh[2][nb][ci] = bh[256 + j];
        }

#pragma unroll
    for (int m = 0; m < 2; m++) {
#pragma unroll
        for (int h8 = 0; h8 < 2; h8++) {
            int gm = mb + wm * 32 + m * 16 + lane4 + h8 * 8;
            int ob = gm / NNODE;
            int on = gm - ob * NNODE;
            size_t obase = WOUT ? ((size_t)((ob * TT + t) * NNODE + on) * HH) : 0;
#pragma unroll
            for (int nb = 0; nb < 2; nb++) {
                int j0 = w16 * 16 + nb * 8 + jq;
                int base = ((w16 * 6 + wm * 2 + m) * 2) * 128 + lane * 4 + (nb * 2 + h8);
                float2 hp = unsplit(HF[base], HF[base + 128]);
                int c = h8 * 2;
                float hv[2];
#pragma unroll
                for (int ci = 0; ci < 2; ci++) {
                    float ir = GIS[(((m * 6 + nb) * 4) + c + ci) * NTH + tid]     + BI[0][nb][ci];
                    float iz = GIS[(((m * 6 + nb + 2) * 4) + c + ci) * NTH + tid] + BI[1][nb][ci];
                    float in_ = GIS[(((m * 6 + nb + 4) * 4) + c + ci) * NTH + tid] + BI[2][nb][ci];
                    float hr = acc1[m][nb][c + ci]     + BHh[0][nb][ci];
                    float hz = acc1[m][nb + 2][c + ci] + BHh[1][nb][ci];
                    float hn = acc1[m][nb + 4][c + ci] + BHh[2][nb][ci];
                    float r = fsigmoid(ir + hr);
                    float z = fsigmoid(iz + hz);
                    float nn = ftanh(in_ + r * hn);
                    float hpv = ci ? hp.y : hp.x;
                    hv[ci] = (1.f - z) * nn + z * hpv;
                }
                unsigned hi, lo;
                split_pack(hv[0], hv[1], hi, lo);
                HF[base] = hi;
                HF[base + 128] = lo;
                st_peer(peerHF + base * 4, hi);
                st_peer(peerHF + (base + 128) * 4, lo);
                if (WOUT)
                    *(float2*)&Oout[obase + j0] = make_float2(hv[0], hv[1]);
                if (write_fin)
                    *(float2*)&Hfin[(size_t)gm * HH + j0] = make_float2(hv[0], hv[1]);
            }
        }
    }
}

// persistent kernel: all 64 timesteps, both layers; H state in smem frags;
// single live accumulator set (gi stashed in smem between spans).
__global__ void __launch_bounds__(NTH, 1) __cluster_dims__(1, 2, 1)
gru_persist(const float* __restrict__ x,
            const float* __restrict__ bih0, const float* __restrict__ bhh0,
            const float* __restrict__ bih1, const float* __restrict__ bhh1,
            float* __restrict__ out, float* __restrict__ h0f, float* __restrict__ h1f)
{
    extern __shared__ unsigned sm[];
    unsigned* XF = sm + XF_OFF;
    unsigned* H0F = sm + H0F_OFF;
    unsigned* H1F = sm + H1F_OFF;
    float* BS = (float*)(sm + BIAS_OFF);
    float* GIS = (float*)(sm + GIS_OFF);

    const int tid = threadIdx.x;
    const int mb = blockIdx.x * MTILE;
    const int half = blockIdx.y;
    const int wid = tid >> 5, lane = tid & 31;
    const int wm = wid >> 2, wn = wid & 3;
    const int ntb = half * 24 + wn * 6;

    unsigned peer_h0, peer_h1, rank;
    asm("mov.u32 %0, %%cluster_ctarank;" : "=r"(rank));
    {
        unsigned a0, a1;
        asm("{ .reg .u64 t; cvta.to.shared.u64 t, %1; cvt.u32.u64 %0, t; }"
            : "=r"(a0) : "l"(H0F));
        asm("{ .reg .u64 t; cvta.to.shared.u64 t, %1; cvt.u32.u64 %0, t; }"
            : "=r"(a1) : "l"(H1F));
        unsigned pr = rank ^ 1;
        asm("mapa.shared::cluster.u32 %0, %1, %2;" : "=r"(peer_h0) : "r"(a0), "r"(pr));
        asm("mapa.shared::cluster.u32 %0, %1, %2;" : "=r"(peer_h1) : "r"(a1), "r"(pr));
    }

    // init: h0 = h1 = 0 ; stage biases
    for (int i = tid; i < 24576; i += NTH) H0F[i] = 0u;
    for (int i = tid; i < 384; i += NTH) {
        BS[i]        = bih0[i];
        BS[384 + i]  = bhh0[i];
        BS[768 + i]  = bih1[i];
        BS[1152 + i] = bhh1[i];
    }
    __syncthreads();

    const uint2* wpb = (const uint2*)g_wp;
    const uint2* w0ih = wpb + WPU2_L0IH;
    const uint2* w0hh = wpb + WPU2_L0HH;
    const uint2* w1ih = wpb + WPU2_L1IH;
    const uint2* w1hh = wpb + WPU2_L1HH;

    float acc[2][6][4];

#pragma unroll 1
    for (int t = 0; t < TT; t++) {
        load_x(XF, x, mb, t, tid);
        __syncthreads();

        // ---- layer 0 ----
#pragma unroll
        for (int m = 0; m < 2; m++)
#pragma unroll
            for (int n = 0; n < 6; n++)
#pragma unroll
                for (int c = 0; c < 4; c++) acc[m][n][c] = 0.f;
        mma_span<4>(XF, w0ih, ntb, wm, lane, acc);
        stash_acc(GIS, acc, tid);
#pragma unroll
        for (int m = 0; m < 2; m++)
#pragma unroll
            for (int n = 0; n < 6; n++)
#pragma unroll
                for (int c = 0; c < 4; c++) acc[m][n][c] = 0.f;
        mma_span<8>(H0F, w0hh, ntb, wm, lane, acc);
        cluster_sync_();                             // B1: peers done reading old H0F
        gru_epilogue<false>(H0F, peer_h0, GIS, acc, BS, BS + 384,
                            (float*)nullptr, h0f, t, mb, half, wm, wn, lane, tid,
                            t == TT - 1);
        cluster_sync_();                             // B2: new H0F visible

        // ---- layer 1 ----
#pragma unroll
        for (int m = 0; m < 2; m++)
#pragma unroll
            for (int n = 0; n < 6; n++)
#pragma unroll
                for (int c = 0; c < 4; c++) acc[m][n][c] = 0.f;
        mma_span<8>(H0F, w1ih, ntb, wm, lane, acc);
        stash_acc(GIS, acc, tid);
#pragma unroll
        for (int m = 0; m < 2; m++)
#pragma unroll
            for (int n = 0; n < 6; n++)
#pragma unroll
                for (int c = 0; c < 4; c++) acc[m][n][c] = 0.f;
        mma_span<8>(H1F, w1hh, ntb, wm, lane, acc);
        cluster_sync_();                             // B3: peers done reading old H1F
        gru_epilogue<true>(H1F, peer_h1, GIS, acc, BS + 768, BS + 1152,
                           out, h1f, t, mb, half, wm, wn, lane, tid, t == TT - 1);
        // epi1 H1F writes ordered for peer by next step's B1+B2
    }

    // FINAL cluster barrier: peer DSMEM stores must land before exit
    cluster_sync_();
}

extern "C" void kernel_launch(void* const* d_in, const int* in_sizes, int n_in,
                              void* d_out, int out_size)
{
    const float* x    = (const float*)d_in[0];
    const float* Wih0 = (const float*)d_in[1];
    const float* Whh0 = (const float*)d_in[2];
    const float* bih0 = (const float*)d_in[3];
    const float* bhh0 = (const float*)d_in[4];
    const float* Wih1 = (const float*)d_in[5];
    const float* Whh1 = (const float*)d_in[6];
    const float* bih1 = (const float*)d_in[7];
    const float* bhh1 = (const float*)d_in[8];

    float* out = (float*)d_out;
    float* h0f = out + (size_t)BB * TT * NNODE * HH;
    float* h1f = h0f + (size_t)MM * HH;

    cudaFuncSetAttribute((const void*)gru_persist,
                         cudaFuncAttributeMaxDynamicSharedMemorySize, SM_U32 * 4);

    prep_kernel<<<168, 256>>>(Wih0, Whh0, Wih1, Whh1);
    gru_persist<<<dim3(GRIDM, 2), NTH, SM_U32 * 4>>>(
        x, bih0, bhh0, bih1, bhh1, out, h0f, h1f);
}